// round 1
// baseline (speedup 1.0000x reference)
#include <cuda_runtime.h>
#include <cuda_bf16.h>
#include <cstdint>

#define N_NODES 50000
#define E_EDGES 800000
#define D 128
#define GN_EPS 1e-5f

// ---------------- scratch (static __device__, no allocation) ----------------
__device__ float g_t[(size_t)N_NODES * D];   // GEMM output (pre-aggregation)
__device__ float g_h[(size_t)N_NODES * D];   // aggregation output / layer input
__device__ float g_deg[N_NODES];
__device__ float g_dinv[N_NODES];
__device__ float g_cs[D];
__device__ float g_css[D];
__device__ float g_scale[D];
__device__ float g_shift[D];

// ---------------- degree / norm coefficients ----------------
__global__ void deg_init_k(int n) {
    int i = blockIdx.x * blockDim.x + threadIdx.x;
    if (i < n) g_deg[i] = 1.0f;   // self loop
}

__global__ void deg_count_k(const int* __restrict__ dst, int e) {
    int i = blockIdx.x * blockDim.x + threadIdx.x;
    if (i < e) atomicAdd(&g_deg[dst[i]], 1.0f);
}

__global__ void dinv_k(int n) {
    int i = blockIdx.x * blockDim.x + threadIdx.x;
    if (i < n) g_dinv[i] = rsqrtf(g_deg[i]);
}

// ---------------- SGEMM: [M,128] @ [128,128] -> g_t ----------------
// A == nullptr means read from g_h (layers 2,3).
#define BM 64
#define BK 32
__global__ void __launch_bounds__(256) gemm_k(const float* __restrict__ A,
                                              const float* __restrict__ W, int M) {
    __shared__ float xs[BM][BK + 1];
    __shared__ float ws[BK][D];
    const float* __restrict__ a_ptr = A ? A : g_h;

    int tid  = threadIdx.x;
    int tcol = tid & 31;    // col micro-tile: cols tcol*4 .. +3
    int trow = tid >> 5;    // row micro-tile: rows trow*8 .. +7
    int row0 = blockIdx.x * BM;

    float acc[8][4];
#pragma unroll
    for (int i = 0; i < 8; i++)
#pragma unroll
        for (int j = 0; j < 4; j++) acc[i][j] = 0.0f;

    for (int kk = 0; kk < D; kk += BK) {
        // load x chunk 64x32 (coalesced)
#pragma unroll
        for (int i = 0; i < 8; i++) {
            int idx = tid + i * 256;
            int r = idx >> 5, k = idx & 31;
            int gr = row0 + r;
            xs[r][k] = (gr < M) ? a_ptr[(size_t)gr * D + kk + k] : 0.0f;
        }
        // load W chunk 32x128 (coalesced)
#pragma unroll
        for (int i = 0; i < 16; i++) {
            int idx = tid + i * 256;
            int k = idx >> 7, c = idx & 127;
            ws[k][c] = W[(size_t)(kk + k) * D + c];
        }
        __syncthreads();
#pragma unroll
        for (int k = 0; k < BK; k++) {
            float4 wv = *(const float4*)&ws[k][tcol * 4];
#pragma unroll
            for (int i = 0; i < 8; i++) {
                float a = xs[trow * 8 + i][k];
                acc[i][0] += a * wv.x;
                acc[i][1] += a * wv.y;
                acc[i][2] += a * wv.z;
                acc[i][3] += a * wv.w;
            }
        }
        __syncthreads();
    }
#pragma unroll
    for (int i = 0; i < 8; i++) {
        int gr = row0 + trow * 8 + i;
        if (gr < M) {
            float4 o = make_float4(acc[i][0], acc[i][1], acc[i][2], acc[i][3]);
            *(float4*)&g_t[(size_t)gr * D + tcol * 4] = o;
        }
    }
}

// ---------------- aggregation: self-loop init + bias, zero stats ----------------
__global__ void agg_init_k(const float* __restrict__ b, int n) {
    if (blockIdx.x == 0 && threadIdx.x < D) {
        g_cs[threadIdx.x] = 0.0f;
        g_css[threadIdx.x] = 0.0f;
    }
    int idx = blockIdx.x * blockDim.x + threadIdx.x;
    int total = n * (D / 4);
    if (idx >= total) return;
    int node = idx >> 5;          // D/4 == 32
    int c4 = (idx & 31) * 4;
    float di = g_dinv[node];
    float coef = di * di;
    float4 h = *(const float4*)&g_t[(size_t)node * D + c4];
    float4 bb = *(const float4*)&b[c4];
    float4 o = make_float4(h.x * coef + bb.x, h.y * coef + bb.y,
                           h.z * coef + bb.z, h.w * coef + bb.w);
    *(float4*)&g_h[(size_t)node * D + c4] = o;
}

// ---------------- edge scatter: one warp per edge, vectorized red ----------------
__global__ void scatter_k(const int* __restrict__ src, const int* __restrict__ dst, int e) {
    int wid = (blockIdx.x * blockDim.x + threadIdx.x) >> 5;
    int lane = threadIdx.x & 31;
    if (wid >= e) return;
    int s = src[wid], d = dst[wid];
    float coef = g_dinv[s] * g_dinv[d];
    float4 h = *(const float4*)&g_t[(size_t)s * D + lane * 4];
    float4 v = make_float4(h.x * coef, h.y * coef, h.z * coef, h.w * coef);
    float* p = &g_h[(size_t)d * D + lane * 4];
    asm volatile("red.global.add.v4.f32 [%0], {%1,%2,%3,%4};"
                 :: "l"(p), "f"(v.x), "f"(v.y), "f"(v.z), "f"(v.w) : "memory");
}

// ---------------- GraphNorm stats: per-column sum & sumsq ----------------
__global__ void stats_k(int n) {
    int c = threadIdx.x;   // 128 threads
    float s = 0.0f, ss = 0.0f;
    for (int r = blockIdx.x; r < n; r += gridDim.x) {
        float v = g_h[(size_t)r * D + c];
        s += v;
        ss += v * v;
    }
    atomicAdd(&g_cs[c], s);
    atomicAdd(&g_css[c], ss);
}

__global__ void finalize_k(const float* __restrict__ w, const float* __restrict__ b,
                           const float* __restrict__ a, int n) {
    int c = threadIdx.x;
    float inv_n = 1.0f / (float)n;
    float m = g_cs[c] * inv_n;
    float msq = g_css[c] * inv_n;
    float al = a[c];
    // var(h - a*m) = E[h^2] - (2a - a^2) m^2
    float var = msq - (2.0f * al - al * al) * m * m;
    float sc = rsqrtf(var + GN_EPS) * w[c];
    g_scale[c] = sc;
    g_shift[c] = b[c] - al * m * sc;
}

__global__ void norm_relu_k(int n) {
    int idx = blockIdx.x * blockDim.x + threadIdx.x;
    int total = n * (D / 4);
    if (idx >= total) return;
    int node = idx >> 5;
    int c4 = (idx & 31) * 4;
    float4 h = *(const float4*)&g_h[(size_t)node * D + c4];
    float4 sc = *(const float4*)&g_scale[c4];
    float4 sh = *(const float4*)&g_shift[c4];
    float4 o;
    o.x = fmaxf(h.x * sc.x + sh.x, 0.0f);
    o.y = fmaxf(h.y * sc.y + sh.y, 0.0f);
    o.z = fmaxf(h.z * sc.z + sh.z, 0.0f);
    o.w = fmaxf(h.w * sc.w + sh.w, 0.0f);
    *(float4*)&g_h[(size_t)node * D + c4] = o;
}

// ---------------- output head: [N,128] @ [128,2] + bout ----------------
__global__ void head_k(const float* __restrict__ Wout, const float* __restrict__ bout,
                       float* __restrict__ out, int n) {
    int wid = (blockIdx.x * blockDim.x + threadIdx.x) >> 5;
    int lane = threadIdx.x & 31;
    if (wid >= n) return;
    float4 h = *(const float4*)&g_h[(size_t)wid * D + lane * 4];
    float a0 = 0.0f, a1 = 0.0f;
    const float* hv = (const float*)&h;
#pragma unroll
    for (int j = 0; j < 4; j++) {
        int k = lane * 4 + j;
        a0 += hv[j] * __ldg(&Wout[k * 2 + 0]);
        a1 += hv[j] * __ldg(&Wout[k * 2 + 1]);
    }
#pragma unroll
    for (int off = 16; off > 0; off >>= 1) {
        a0 += __shfl_down_sync(0xFFFFFFFFu, a0, off);
        a1 += __shfl_down_sync(0xFFFFFFFFu, a1, off);
    }
    if (lane == 0) {
        out[(size_t)wid * 2 + 0] = a0 + bout[0];
        out[(size_t)wid * 2 + 1] = a1 + bout[1];
    }
}

// ---------------- launch ----------------
extern "C" void kernel_launch(void* const* d_in, const int* in_sizes, int n_in,
                              void* d_out, int out_size) {
    const float* x    = (const float*)d_in[0];
    const int*   ei   = (const int*)d_in[1];
    const float* W1   = (const float*)d_in[2];
    const float* b1   = (const float*)d_in[3];
    const float* W2   = (const float*)d_in[4];
    const float* b2   = (const float*)d_in[5];
    const float* W3   = (const float*)d_in[6];
    const float* b3   = (const float*)d_in[7];
    const float* gn1w = (const float*)d_in[8];
    const float* gn1b = (const float*)d_in[9];
    const float* gn1a = (const float*)d_in[10];
    const float* gn2w = (const float*)d_in[11];
    const float* gn2b = (const float*)d_in[12];
    const float* gn2a = (const float*)d_in[13];
    const float* Wout = (const float*)d_in[14];
    const float* bout = (const float*)d_in[15];

    int n = in_sizes[0] / D;      // 50000
    int e = in_sizes[1] / 2;      // 800000
    const int* src = ei;
    const int* dst = ei + e;

    int nd4_blocks   = (n * (D / 4) + 255) / 256;
    int gemm_blocks  = (n + BM - 1) / BM;
    int edge_blocks  = (int)(((long long)e * 32 + 255) / 256);
    int node_blocks  = (n + 255) / 256;
    int nwarp_blocks = (int)(((long long)n * 32 + 255) / 256);

    // degrees / normalization coefficients
    deg_init_k<<<node_blocks, 256>>>(n);
    deg_count_k<<<(e + 255) / 256, 256>>>(dst, e);
    dinv_k<<<node_blocks, 256>>>(n);

    // ---- layer 1 ----
    gemm_k<<<gemm_blocks, 256>>>(x, W1, n);
    agg_init_k<<<nd4_blocks, 256>>>(b1, n);
    scatter_k<<<edge_blocks, 256>>>(src, dst, e);
    stats_k<<<1024, 128>>>(n);
    finalize_k<<<1, 128>>>(gn1w, gn1b, gn1a, n);
    norm_relu_k<<<nd4_blocks, 256>>>(n);

    // ---- layer 2 ----
    gemm_k<<<gemm_blocks, 256>>>(nullptr, W2, n);
    agg_init_k<<<nd4_blocks, 256>>>(b2, n);
    scatter_k<<<edge_blocks, 256>>>(src, dst, e);
    stats_k<<<1024, 128>>>(n);
    finalize_k<<<1, 128>>>(gn2w, gn2b, gn2a, n);
    norm_relu_k<<<nd4_blocks, 256>>>(n);

    // ---- layer 3 ----
    gemm_k<<<gemm_blocks, 256>>>(nullptr, W3, n);
    agg_init_k<<<nd4_blocks, 256>>>(b3, n);
    scatter_k<<<edge_blocks, 256>>>(src, dst, e);

    // ---- output head ----
    head_k<<<nwarp_blocks, 256>>>(Wout, bout, (float*)d_out, n);
}